// round 2
// baseline (speedup 1.0000x reference)
#include <cuda_runtime.h>

// EMA scan: s_t = 0.9*s_{t-1} + 0.1*x_t
// x: (T=1024, 32, 1024) f32, state: (32, 1024) f32
// out buffer: out (T*32768 floats) followed by final_state (32768 floats)
//
// Parallelization: T split into two chunks at t=576.
//   chunk 0: t in [0,576), starts from real state, stores all.
//   chunk 1: warm-up on [448,576) starting from s=0 (error 0.9^128 ~ 1.4e-6),
//            then stores [576,1024) and the final state.
// Both chunks load exactly 576 timesteps -> balanced.
// Loads are double-buffered (prefetch next 16 while computing current 16).

#define T_STEPS 1024
#define N_CH    32768
#define U       16
#define SPLIT   576
#define WARM    128

__device__ __forceinline__
float run_span(const float* __restrict__ xp, float* __restrict__ op,
               float s, int t0, int t1, bool do_store)
{
    float cur[U], nxt[U];

    #pragma unroll
    for (int u = 0; u < U; u++)
        cur[u] = xp[(size_t)(t0 + u) * N_CH];

    #pragma unroll 1
    for (int t = t0; t < t1; t += U) {
        const int tn = t + U;
        if (tn < t1) {
            #pragma unroll
            for (int u = 0; u < U; u++)
                nxt[u] = xp[(size_t)(tn + u) * N_CH];
        }
        #pragma unroll
        for (int u = 0; u < U; u++) {
            s = fmaf(s, 0.9f, cur[u] * 0.1f);
            if (do_store)
                op[(size_t)(t + u) * N_CH] = s;
        }
        #pragma unroll
        for (int u = 0; u < U; u++)
            cur[u] = nxt[u];
    }
    return s;
}

__global__ __launch_bounds__(256, 2)
void ema_scan_kernel(const float* __restrict__ x,
                     const float* __restrict__ state,
                     float* __restrict__ out)
{
    const int tid  = blockIdx.x * 256 + threadIdx.x;   // 0..65535
    const int c    = tid & (N_CH - 1);                 // channel
    const int half = tid >> 15;                        // 0 or 1

    const float* xp = x + c;
    float*       op = out + c;

    if (half == 0) {
        // chunk 0: exact scan [0, SPLIT)
        float s = state[c];
        run_span(xp, op, s, 0, SPLIT, true);
    } else {
        // chunk 1: warm-up [SPLIT-WARM, SPLIT) from s=0, then store [SPLIT, T)
        float s = 0.0f;
        s = run_span(xp, op, s, SPLIT - WARM, SPLIT, false);
        s = run_span(xp, op, s, SPLIT, T_STEPS, true);
        // final_state appended after out
        out[(size_t)T_STEPS * N_CH + c] = s;
    }
}

extern "C" void kernel_launch(void* const* d_in, const int* in_sizes, int n_in,
                              void* d_out, int out_size)
{
    const float* x     = (const float*)d_in[0];
    const float* state = (const float*)d_in[1];
    float*       out   = (float*)d_out;

    dim3 block(256);
    dim3 grid((2 * N_CH) / 256);   // 256 CTAs: 2 T-chunks x 32768 channels
    ema_scan_kernel<<<grid, block>>>(x, state, out);
}